// round 1
// baseline (speedup 1.0000x reference)
#include <cuda_runtime.h>
#include <cstdint>

// Problem dims (fixed)
#define Bq   8
#define Tq   2048
#define Cq   1024
#define HIDq 4096
#define Mq   (Bq*Tq)        // 16384 rows
#define NCH  32             // WKV chunks
#define LCH  (Tq/NCH)       // 64 steps per chunk

// ---------------- scratch (static device globals; no allocation) ----------
__device__ float g_xk[(size_t)Mq*Cq];
__device__ float g_xv[(size_t)Mq*Cq];
__device__ float g_xr[(size_t)Mq*Cq];
__device__ float g_k [(size_t)Mq*Cq];
__device__ float g_v [(size_t)Mq*Cq];
__device__ float g_sr[(size_t)Mq*Cq];
__device__ float g_rw[(size_t)Mq*Cq];
__device__ float g_x1[(size_t)Mq*Cq];
__device__ float g_fk[(size_t)Mq*Cq];
__device__ float g_fr[(size_t)Mq*Cq];
__device__ float g_sg[(size_t)Mq*Cq];
__device__ float g_kk[(size_t)Mq*HIDq];
__device__ float g_Ca[(size_t)NCH*Bq*Cq];
__device__ float g_Cb[(size_t)NCH*Bq*Cq];
__device__ float g_Sa[(size_t)NCH*Bq*Cq];
__device__ float g_Sb[(size_t)NCH*Bq*Cq];

// ---------------- helpers --------------------------------------------------
__device__ __forceinline__ uint32_t f2tf(float x) {
    uint32_t r;
    asm("cvt.rna.tf32.f32 %0, %1;" : "=r"(r) : "f"(x));
    return r;
}

__device__ __forceinline__ void mma_tf32(float* c, const uint32_t* a, const uint32_t* b) {
    asm volatile(
        "mma.sync.aligned.m16n8k8.row.col.f32.tf32.tf32.f32 "
        "{%0,%1,%2,%3}, {%4,%5,%6,%7}, {%8,%9}, {%0,%1,%2,%3};"
        : "+f"(c[0]), "+f"(c[1]), "+f"(c[2]), "+f"(c[3])
        : "r"(a[0]), "r"(a[1]), "r"(a[2]), "r"(a[3]), "r"(b[0]), "r"(b[1]));
}

// block-wide reduce of 4 values (256 threads)
__device__ __forceinline__ void bred4(float& a, float& b, float& c, float& d) {
    #pragma unroll
    for (int o = 16; o; o >>= 1) {
        a += __shfl_xor_sync(0xffffffffu, a, o);
        b += __shfl_xor_sync(0xffffffffu, b, o);
        c += __shfl_xor_sync(0xffffffffu, c, o);
        d += __shfl_xor_sync(0xffffffffu, d, o);
    }
    __shared__ float sm[8][4];
    int w = threadIdx.x >> 5, l = threadIdx.x & 31;
    if (l == 0) { sm[w][0] = a; sm[w][1] = b; sm[w][2] = c; sm[w][3] = d; }
    __syncthreads();
    a = b = c = d = 0.f;
    #pragma unroll
    for (int j = 0; j < 8; j++) { a += sm[j][0]; b += sm[j][1]; c += sm[j][2]; d += sm[j][3]; }
}

// ---------------- fused LayerNorm + time-shift + token-mix -----------------
// NOUT=3: (xk, xv, xr) for att branch; NOUT=2: (fk, fr) for ffn branch.
template<int NOUT>
__global__ __launch_bounds__(256) void ln_mix(
    const float* __restrict__ x, const float* __restrict__ g, const float* __restrict__ be,
    const float* __restrict__ m0, const float* __restrict__ m1, const float* __restrict__ m2,
    float* __restrict__ o0, float* __restrict__ o1, float* __restrict__ o2)
{
    const int row = blockIdx.x;          // b*T + t
    const int t   = row & (Tq - 1);
    const int i   = threadIdx.x;         // one float4 per thread (C/4 = 256)

    const float4 v = reinterpret_cast<const float4*>(x + (size_t)row * Cq)[i];
    float4 u = make_float4(0.f, 0.f, 0.f, 0.f);
    if (t > 0) u = reinterpret_cast<const float4*>(x + (size_t)(row - 1) * Cq)[i];

    float s  = v.x + v.y + v.z + v.w;
    float ss = v.x*v.x + v.y*v.y + v.z*v.z + v.w*v.w;
    float sp = u.x + u.y + u.z + u.w;
    float sq = u.x*u.x + u.y*u.y + u.z*u.z + u.w*u.w;
    bred4(s, ss, sp, sq);

    const float inv = 1.f / (float)Cq;
    const float mC = s * inv;
    const float rs = rsqrtf(ss * inv - mC * mC + 1e-5f);
    const float mP = sp * inv;
    const float rp = rsqrtf(sq * inv - mP * mP + 1e-5f);

    const float4 g4 = reinterpret_cast<const float4*>(g)[i];
    const float4 b4 = reinterpret_cast<const float4*>(be)[i];

    float xa[4], xx[4];
    const float* vv = &v.x; const float* uu = &u.x;
    const float* gg = &g4.x; const float* bb = &b4.x;
    #pragma unroll
    for (int j = 0; j < 4; j++) {
        xa[j] = (vv[j] - mC) * rs * gg[j] + bb[j];
        xx[j] = (t > 0) ? ((uu[j] - mP) * rp * gg[j] + bb[j]) : 0.f;
    }

    const size_t oi = (size_t)row * (Cq / 4) + i;
    {
        const float4 w4 = reinterpret_cast<const float4*>(m0)[i];
        const float* ww = &w4.x; float4 r;
        float* rr = &r.x;
        #pragma unroll
        for (int j = 0; j < 4; j++) rr[j] = xa[j] * ww[j] + xx[j] * (1.f - ww[j]);
        reinterpret_cast<float4*>(o0)[oi] = r;
    }
    {
        const float4 w4 = reinterpret_cast<const float4*>(m1)[i];
        const float* ww = &w4.x; float4 r;
        float* rr = &r.x;
        #pragma unroll
        for (int j = 0; j < 4; j++) rr[j] = xa[j] * ww[j] + xx[j] * (1.f - ww[j]);
        reinterpret_cast<float4*>(o1)[oi] = r;
    }
    if (NOUT == 3) {
        const float4 w4 = reinterpret_cast<const float4*>(m2)[i];
        const float* ww = &w4.x; float4 r;
        float* rr = &r.x;
        #pragma unroll
        for (int j = 0; j < 4; j++) rr[j] = xa[j] * ww[j] + xx[j] * (1.f - ww[j]);
        reinterpret_cast<float4*>(o2)[oi] = r;
    }
}

// ---------------- tf32 GEMM: out[m,n] = sum_k A[m,k]*W[n,k], fused epilogue -
// EPI: 0 none | 1 sigmoid | 2 relu^2 | 3 aux1+acc | 4 aux1 + aux2*acc
#define BM  128
#define BN  128
#define BKK 32
#define PADq 4

template<int EPI>
__device__ __forceinline__ void epi_store(float* __restrict__ out, size_t idx,
    float c0, float c1, const float* __restrict__ a1, const float* __restrict__ a2)
{
    if (EPI == 1) { c0 = 1.f / (1.f + __expf(-c0)); c1 = 1.f / (1.f + __expf(-c1)); }
    else if (EPI == 2) { c0 = fmaxf(c0, 0.f); c0 *= c0; c1 = fmaxf(c1, 0.f); c1 *= c1; }
    else if (EPI == 3) { c0 += a1[idx]; c1 += a1[idx + 1]; }
    else if (EPI == 4) { c0 = a1[idx] + a2[idx] * c0; c1 = a1[idx + 1] + a2[idx + 1] * c1; }
    float2 t; t.x = c0; t.y = c1;
    *reinterpret_cast<float2*>(out + idx) = t;
}

template<int EPI>
__global__ __launch_bounds__(256) void gemm_tf32(
    const float* __restrict__ A, const float* __restrict__ W, float* __restrict__ out,
    const float* __restrict__ aux1, const float* __restrict__ aux2, int N, int K)
{
    __shared__ uint32_t As[BM][BKK + PADq];
    __shared__ uint32_t Bs[BN][BKK + PADq];

    const int tid  = threadIdx.x;
    const int lane = tid & 31;
    const int warp = tid >> 5;
    const int wm   = warp >> 1;   // 0..3 -> 32 rows each
    const int wn   = warp & 1;    // 0..1 -> 64 cols each

    const int brow = blockIdx.y * BM;
    const int bcol = blockIdx.x * BN;
    const float* Ag = A + (size_t)brow * K;
    const float* Wg = W + (size_t)bcol * K;

    float acc[2][8][4];
    #pragma unroll
    for (int mt = 0; mt < 2; mt++)
        #pragma unroll
        for (int nt = 0; nt < 8; nt++)
            #pragma unroll
            for (int q = 0; q < 4; q++) acc[mt][nt][q] = 0.f;

    const int lr = tid >> 3;          // 0..31
    const int lc = (tid & 7) * 4;     // 0,4,...,28

    for (int k0 = 0; k0 < K; k0 += BKK) {
        #pragma unroll
        for (int p = 0; p < 4; p++) {
            const int r = lr + p * 32;
            float4 av = *reinterpret_cast<const float4*>(Ag + (size_t)r * K + k0 + lc);
            *reinterpret_cast<uint4*>(&As[r][lc]) =
                make_uint4(f2tf(av.x), f2tf(av.y), f2tf(av.z), f2tf(av.w));
            float4 bv = *reinterpret_cast<const float4*>(Wg + (size_t)r * K + k0 + lc);
            *reinterpret_cast<uint4*>(&Bs[r][lc]) =
                make_uint4(f2tf(bv.x), f2tf(bv.y), f2tf(bv.z), f2tf(bv.w));
        }
        __syncthreads();

        #pragma unroll
        for (int ks = 0; ks < 4; ks++) {
            const int k8 = ks * 8;
            uint32_t a[2][4], b[8][2];
            #pragma unroll
            for (int mt = 0; mt < 2; mt++) {
                const int r0 = wm * 32 + mt * 16;
                a[mt][0] = As[r0 +     (lane >> 2)][k8 +     (lane & 3)];
                a[mt][1] = As[r0 + 8 + (lane >> 2)][k8 +     (lane & 3)];
                a[mt][2] = As[r0 +     (lane >> 2)][k8 + 4 + (lane & 3)];
                a[mt][3] = As[r0 + 8 + (lane >> 2)][k8 + 4 + (lane & 3)];
            }
            #pragma unroll
            for (int nt = 0; nt < 8; nt++) {
                const int c0 = wn * 64 + nt * 8;
                b[nt][0] = Bs[c0 + (lane >> 2)][k8 +     (lane & 3)];
                b[nt][1] = Bs[c0 + (lane >> 2)][k8 + 4 + (lane & 3)];
            }
            #pragma unroll
            for (int mt = 0; mt < 2; mt++)
                #pragma unroll
                for (int nt = 0; nt < 8; nt++)
                    mma_tf32(acc[mt][nt], a[mt], b[nt]);
        }
        __syncthreads();
    }

    // epilogue straight from registers (known m16n8k8 acc layout)
    #pragma unroll
    for (int mt = 0; mt < 2; mt++) {
        #pragma unroll
        for (int nt = 0; nt < 8; nt++) {
            const int row = brow + wm * 32 + mt * 16 + (lane >> 2);
            const int col = bcol + wn * 64 + nt * 8 + (lane & 3) * 2;
            const size_t i0 = (size_t)row * N + col;
            const size_t i1 = (size_t)(row + 8) * N + col;
            epi_store<EPI>(out, i0, acc[mt][nt][0], acc[mt][nt][1], aux1, aux2);
            epi_store<EPI>(out, i1, acc[mt][nt][2], acc[mt][nt][3], aux1, aux2);
        }
    }
}

// ---------------- WKV chunked scan ------------------------------------------
// Un-stabilized affine recurrence: a' = e^w a + e^k v ; chunk decay e^{L w} known.
__global__ __launch_bounds__(256) void wkv_phase_a(
    const float* __restrict__ k, const float* __restrict__ v,
    const float* __restrict__ td, float* __restrict__ Ca, float* __restrict__ Cb)
{
    const int gid = blockIdx.x * blockDim.x + threadIdx.x;   // < NCH*B*C
    const int c  = gid & (Cq - 1);
    const int r  = gid >> 10;
    const int b  = r & (Bq - 1);
    const int ch = r >> 3;
    const float w  = -expf(td[c]);
    const float dw = expf(w);
    const size_t base = ((size_t)(b * Tq + ch * LCH)) * Cq + c;
    float sa = 0.f, sb = 0.f;
    #pragma unroll 4
    for (int i = 0; i < LCH; i++) {
        const float kt = k[base + (size_t)i * Cq];
        const float vt = v[base + (size_t)i * Cq];
        const float ek = __expf(kt);
        sa = fmaf(dw, sa, ek * vt);
        sb = fmaf(dw, sb, ek);
    }
    Ca[gid] = sa; Cb[gid] = sb;
}

__global__ __launch_bounds__(256) void wkv_scan(
    const float* __restrict__ td,
    const float* __restrict__ Ca, const float* __restrict__ Cb,
    float* __restrict__ Sa, float* __restrict__ Sb)
{
    const int sid = blockIdx.x * blockDim.x + threadIdx.x;   // < B*C
    const int c = sid & (Cq - 1);
    const float w  = -expf(td[c]);
    const float dL = expf((float)LCH * w);
    float sa = 0.f, sb = 0.f;
    #pragma unroll
    for (int ch = 0; ch < NCH; ch++) {
        const int idx = ch * (Bq * Cq) + sid;
        Sa[idx] = sa; Sb[idx] = sb;
        sa = fmaf(dL, sa, Ca[idx]);
        sb = fmaf(dL, sb, Cb[idx]);
    }
}

__global__ __launch_bounds__(256) void wkv_phase_b(
    const float* __restrict__ k, const float* __restrict__ v, const float* __restrict__ sr,
    const float* __restrict__ td, const float* __restrict__ tf,
    const float* __restrict__ Sa, const float* __restrict__ Sb, float* __restrict__ out)
{
    const int gid = blockIdx.x * blockDim.x + threadIdx.x;
    const int c  = gid & (Cq - 1);
    const int r  = gid >> 10;
    const int b  = r & (Bq - 1);
    const int ch = r >> 3;
    const float w  = -expf(td[c]);
    const float dw = expf(w);
    const float eu = expf(tf[c]);
    float a = Sa[gid], bb = Sb[gid];
    const size_t base = ((size_t)(b * Tq + ch * LCH)) * Cq + c;
    #pragma unroll 4
    for (int i = 0; i < LCH; i++) {
        const size_t off = base + (size_t)i * Cq;
        const float kt = k[off];
        const float vt = v[off];
        const float ek = __expf(kt);
        const float euk = eu * ek;
        const float y = (a + euk * vt) / (bb + euk);
        out[off] = sr[off] * y;
        a  = fmaf(dw, a,  ek * vt);
        bb = fmaf(dw, bb, ek);
    }
}

// ---------------- launch -----------------------------------------------------
extern "C" void kernel_launch(void* const* d_in, const int* in_sizes, int n_in,
                              void* d_out, int out_size)
{
    const float* x     = (const float*)d_in[0];
    const float* ln1_g = (const float*)d_in[1];
    const float* ln1_b = (const float*)d_in[2];
    const float* ln2_g = (const float*)d_in[3];
    const float* ln2_b = (const float*)d_in[4];
    const float* td    = (const float*)d_in[5];
    const float* tf    = (const float*)d_in[6];
    const float* tmk   = (const float*)d_in[7];
    const float* tmv   = (const float*)d_in[8];
    const float* tmr   = (const float*)d_in[9];
    const float* Wk    = (const float*)d_in[10];
    const float* Wv    = (const float*)d_in[11];
    const float* Wr    = (const float*)d_in[12];
    const float* Wo    = (const float*)d_in[13];
    const float* fmk   = (const float*)d_in[14];
    const float* fmr   = (const float*)d_in[15];
    const float* Fk    = (const float*)d_in[16];
    const float* Fr    = (const float*)d_in[17];
    const float* Fv    = (const float*)d_in[18];
    float* out = (float*)d_out;

    float *xk, *xv, *xr, *k, *v, *sr, *rw, *x1, *fk, *fr, *sg, *kk, *Ca, *Cb, *Sa, *Sb;
    cudaGetSymbolAddress((void**)&xk, g_xk);
    cudaGetSymbolAddress((void**)&xv, g_xv);
    cudaGetSymbolAddress((void**)&xr, g_xr);
    cudaGetSymbolAddress((void**)&k,  g_k);
    cudaGetSymbolAddress((void**)&v,  g_v);
    cudaGetSymbolAddress((void**)&sr, g_sr);
    cudaGetSymbolAddress((void**)&rw, g_rw);
    cudaGetSymbolAddress((void**)&x1, g_x1);
    cudaGetSymbolAddress((void**)&fk, g_fk);
    cudaGetSymbolAddress((void**)&fr, g_fr);
    cudaGetSymbolAddress((void**)&sg, g_sg);
    cudaGetSymbolAddress((void**)&kk, g_kk);
    cudaGetSymbolAddress((void**)&Ca, g_Ca);
    cudaGetSymbolAddress((void**)&Cb, g_Cb);
    cudaGetSymbolAddress((void**)&Sa, g_Sa);
    cudaGetSymbolAddress((void**)&Sb, g_Sb);

    const dim3 gC(Cq / BN,  Mq / BM);   // (8, 128)  N=1024
    const dim3 gH(HIDq / BN, Mq / BM);  // (32, 128) N=4096

    // att branch
    ln_mix<3><<<Mq, 256>>>(x, ln1_g, ln1_b, tmk, tmv, tmr, xk, xv, xr);
    gemm_tf32<0><<<gC, 256>>>(xk, Wk, k,  nullptr, nullptr, Cq, Cq);
    gemm_tf32<0><<<gC, 256>>>(xv, Wv, v,  nullptr, nullptr, Cq, Cq);
    gemm_tf32<1><<<gC, 256>>>(xr, Wr, sr, nullptr, nullptr, Cq, Cq);

    wkv_phase_a<<<(NCH * Bq * Cq) / 256, 256>>>(k, v, td, Ca, Cb);
    wkv_scan   <<<(Bq * Cq) / 256, 256>>>(td, Ca, Cb, Sa, Sb);
    wkv_phase_b<<<(NCH * Bq * Cq) / 256, 256>>>(k, v, sr, td, tf, Sa, Sb, rw);

    gemm_tf32<3><<<gC, 256>>>(rw, Wo, x1, x, nullptr, Cq, Cq);

    // ffn branch
    ln_mix<2><<<Mq, 256>>>(x1, ln2_g, ln2_b, fmk, fmr, nullptr, fk, fr, nullptr);
    gemm_tf32<2><<<gH, 256>>>(fk, Fk, kk, nullptr, nullptr, HIDq, Cq);
    gemm_tf32<1><<<gC, 256>>>(fr, Fr, sg, nullptr, nullptr, Cq, Cq);
    gemm_tf32<4><<<gC, 256>>>(kk, Fv, out, x1, sg, Cq, HIDq);
}

// round 2
// speedup vs baseline: 1.8265x; 1.8265x over previous
#include <cuda_runtime.h>
#include <cstdint>

// Problem dims (fixed)
#define Bq   8
#define Tq   2048
#define Cq   1024
#define HIDq 4096
#define Mq   (Bq*Tq)        // 16384 rows
#define NCH  32             // WKV chunks
#define LCH  (Tq/NCH)       // 64 steps per chunk

// GEMM tiling
#define BM     128
#define BN     128
#define BKK    32
#define LDW    36           // padded smem row stride (floats) -> conflict-free
#define STAGES 3
#define GEMM_SMEM (STAGES * 2 * 128 * LDW * 4)   // 110592 bytes

// ---------------- scratch (static device globals; no allocation) ----------
__device__ float g_xk[(size_t)Mq*Cq];
__device__ float g_xv[(size_t)Mq*Cq];
__device__ float g_xr[(size_t)Mq*Cq];
__device__ float g_k [(size_t)Mq*Cq];
__device__ float g_v [(size_t)Mq*Cq];
__device__ float g_sr[(size_t)Mq*Cq];
__device__ float g_rw[(size_t)Mq*Cq];
__device__ float g_x1[(size_t)Mq*Cq];
__device__ float g_fk[(size_t)Mq*Cq];
__device__ float g_fr[(size_t)Mq*Cq];
__device__ float g_sg[(size_t)Mq*Cq];
__device__ float g_kk[(size_t)Mq*HIDq];
__device__ float g_Ca[(size_t)NCH*Bq*Cq];
__device__ float g_Cb[(size_t)NCH*Bq*Cq];
__device__ float g_Sa[(size_t)NCH*Bq*Cq];
__device__ float g_Sb[(size_t)NCH*Bq*Cq];
// rounded weight copies: Wk,Wv,Wr,Wo,Fr (C*C each) then Fk,Fv (HID*C each)
__device__ float g_wt[(size_t)5*Cq*Cq + (size_t)2*HIDq*Cq];

// ---------------- helpers --------------------------------------------------
__device__ __forceinline__ uint32_t f2tf(float x) {
    uint32_t r;
    asm("cvt.rna.tf32.f32 %0, %1;" : "=r"(r) : "f"(x));
    return r;
}
__device__ __forceinline__ float rtf(float x) { return __uint_as_float(f2tf(x)); }

__device__ __forceinline__ void mma_tf32(float* c, const uint32_t* a, const uint32_t* b) {
    asm volatile(
        "mma.sync.aligned.m16n8k8.row.col.f32.tf32.tf32.f32 "
        "{%0,%1,%2,%3}, {%4,%5,%6,%7}, {%8,%9}, {%0,%1,%2,%3};"
        : "+f"(c[0]), "+f"(c[1]), "+f"(c[2]), "+f"(c[3])
        : "r"(a[0]), "r"(a[1]), "r"(a[2]), "r"(a[3]), "r"(b[0]), "r"(b[1]));
}

__device__ __forceinline__ uint32_t smem_u32(const void* p) {
    uint32_t a;
    asm("{ .reg .u64 t; cvta.to.shared.u64 t, %1; cvt.u32.u64 %0, t; }" : "=r"(a) : "l"(p));
    return a;
}
__device__ __forceinline__ void cp16(uint32_t dst, const float* src) {
    asm volatile("cp.async.cg.shared.global [%0], [%1], 16;" :: "r"(dst), "l"(src));
}
__device__ __forceinline__ void cp_commit() { asm volatile("cp.async.commit_group;"); }
template<int N> __device__ __forceinline__ void cp_wait() {
    asm volatile("cp.async.wait_group %0;" :: "n"(N));
}

// block-wide reduce of 4 values (256 threads)
__device__ __forceinline__ void bred4(float& a, float& b, float& c, float& d) {
    #pragma unroll
    for (int o = 16; o; o >>= 1) {
        a += __shfl_xor_sync(0xffffffffu, a, o);
        b += __shfl_xor_sync(0xffffffffu, b, o);
        c += __shfl_xor_sync(0xffffffffu, c, o);
        d += __shfl_xor_sync(0xffffffffu, d, o);
    }
    __shared__ float sm[8][4];
    int w = threadIdx.x >> 5, l = threadIdx.x & 31;
    if (l == 0) { sm[w][0] = a; sm[w][1] = b; sm[w][2] = c; sm[w][3] = d; }
    __syncthreads();
    a = b = c = d = 0.f;
    #pragma unroll
    for (int j = 0; j < 8; j++) { a += sm[j][0]; b += sm[j][1]; c += sm[j][2]; d += sm[j][3]; }
}

// ---------------- weight rounding (RNE to tf32, stored as fp32) ------------
__global__ __launch_bounds__(256) void round_copy4(const float* __restrict__ src,
                                                   float* __restrict__ dst, int n4)
{
    const int i = blockIdx.x * blockDim.x + threadIdx.x;
    if (i >= n4) return;
    float4 v = reinterpret_cast<const float4*>(src)[i];
    v.x = rtf(v.x); v.y = rtf(v.y); v.z = rtf(v.z); v.w = rtf(v.w);
    reinterpret_cast<float4*>(dst)[i] = v;
}

// ---------------- fused LayerNorm + time-shift + token-mix -----------------
// Outputs are tf32-RNE rounded (they feed GEMM A operands only).
template<int NOUT>
__global__ __launch_bounds__(256) void ln_mix(
    const float* __restrict__ x, const float* __restrict__ g, const float* __restrict__ be,
    const float* __restrict__ m0, const float* __restrict__ m1, const float* __restrict__ m2,
    float* __restrict__ o0, float* __restrict__ o1, float* __restrict__ o2)
{
    const int row = blockIdx.x;          // b*T + t
    const int t   = row & (Tq - 1);
    const int i   = threadIdx.x;         // one float4 per thread (C/4 = 256)

    const float4 v = reinterpret_cast<const float4*>(x + (size_t)row * Cq)[i];
    float4 u = make_float4(0.f, 0.f, 0.f, 0.f);
    if (t > 0) u = reinterpret_cast<const float4*>(x + (size_t)(row - 1) * Cq)[i];

    float s  = v.x + v.y + v.z + v.w;
    float ss = v.x*v.x + v.y*v.y + v.z*v.z + v.w*v.w;
    float sp = u.x + u.y + u.z + u.w;
    float sq = u.x*u.x + u.y*u.y + u.z*u.z + u.w*u.w;
    bred4(s, ss, sp, sq);

    const float inv = 1.f / (float)Cq;
    const float mC = s * inv;
    const float rs = rsqrtf(ss * inv - mC * mC + 1e-5f);
    const float mP = sp * inv;
    const float rp = rsqrtf(sq * inv - mP * mP + 1e-5f);

    const float4 g4 = reinterpret_cast<const float4*>(g)[i];
    const float4 b4 = reinterpret_cast<const float4*>(be)[i];

    float xa[4], xx[4];
    const float* vv = &v.x; const float* uu = &u.x;
    const float* gg = &g4.x; const float* bb = &b4.x;
    #pragma unroll
    for (int j = 0; j < 4; j++) {
        xa[j] = (vv[j] - mC) * rs * gg[j] + bb[j];
        xx[j] = (t > 0) ? ((uu[j] - mP) * rp * gg[j] + bb[j]) : 0.f;
    }

    const size_t oi = (size_t)row * (Cq / 4) + i;
    {
        const float4 w4 = reinterpret_cast<const float4*>(m0)[i];
        const float* ww = &w4.x; float4 r; float* rr = &r.x;
        #pragma unroll
        for (int j = 0; j < 4; j++) rr[j] = rtf(xa[j] * ww[j] + xx[j] * (1.f - ww[j]));
        reinterpret_cast<float4*>(o0)[oi] = r;
    }
    {
        const float4 w4 = reinterpret_cast<const float4*>(m1)[i];
        const float* ww = &w4.x; float4 r; float* rr = &r.x;
        #pragma unroll
        for (int j = 0; j < 4; j++) rr[j] = rtf(xa[j] * ww[j] + xx[j] * (1.f - ww[j]));
        reinterpret_cast<float4*>(o1)[oi] = r;
    }
    if (NOUT == 3) {
        const float4 w4 = reinterpret_cast<const float4*>(m2)[i];
        const float* ww = &w4.x; float4 r; float* rr = &r.x;
        #pragma unroll
        for (int j = 0; j < 4; j++) rr[j] = rtf(xa[j] * ww[j] + xx[j] * (1.f - ww[j]));
        reinterpret_cast<float4*>(o2)[oi] = r;
    }
}

// ---------------- tf32 GEMM with cp.async 3-stage pipeline -----------------
// out[m,n] = sum_k A[m,k]*W[n,k].  A and W are PRE-ROUNDED to tf32 values, so
// feeding raw fp32 bits into the MMA is exact.
// EPI: 0 none | 1 sigmoid | 2 relu^2 (tf32-rounded) | 3 aux1+acc | 4 aux1+aux2*acc
template<int EPI>
__device__ __forceinline__ void epi_store(float* __restrict__ out, size_t idx,
    float c0, float c1, const float* __restrict__ a1, const float* __restrict__ a2)
{
    if (EPI == 1) { c0 = 1.f / (1.f + __expf(-c0)); c1 = 1.f / (1.f + __expf(-c1)); }
    else if (EPI == 2) {
        c0 = fmaxf(c0, 0.f); c0 = rtf(c0 * c0);
        c1 = fmaxf(c1, 0.f); c1 = rtf(c1 * c1);
    }
    else if (EPI == 3) { c0 += a1[idx]; c1 += a1[idx + 1]; }
    else if (EPI == 4) { c0 = a1[idx] + a2[idx] * c0; c1 = a1[idx + 1] + a2[idx + 1] * c1; }
    float2 t; t.x = c0; t.y = c1;
    *reinterpret_cast<float2*>(out + idx) = t;
}

template<int EPI>
__global__ __launch_bounds__(256, 2) void gemm_tf32(
    const float* __restrict__ A, const float* __restrict__ W, float* __restrict__ out,
    const float* __restrict__ aux1, const float* __restrict__ aux2, int N, int K)
{
    extern __shared__ float smf[];
    float* As = smf;                              // [STAGES][128*LDW]
    float* Bs = smf + (size_t)STAGES * 128 * LDW;

    const int tid  = threadIdx.x;
    const int lane = tid & 31;
    const int warp = tid >> 5;
    const int wm   = warp >> 1;   // 0..3 -> 32 rows
    const int wn   = warp & 1;    // 0..1 -> 64 cols

    const int brow = blockIdx.y * BM;
    const int bcol = blockIdx.x * BN;
    const float* Ag = A + (size_t)brow * K;
    const float* Wg = W + (size_t)bcol * K;

    const int lr = tid >> 3;          // 0..31
    const int lc = (tid & 7) * 4;     // 0,4,...,28

    const uint32_t sA = smem_u32(As);
    const uint32_t sB = smem_u32(Bs);

    const int ntiles = K / BKK;

    // prologue: prefetch first STAGES-1 tiles
    #pragma unroll
    for (int s = 0; s < STAGES - 1; s++) {
        const float* ag = Ag + (size_t)s * BKK;
        const float* wg = Wg + (size_t)s * BKK;
        const uint32_t sa = sA + s * (128 * LDW * 4);
        const uint32_t sb = sB + s * (128 * LDW * 4);
        #pragma unroll
        for (int p = 0; p < 4; p++) {
            const int r = lr + p * 32;
            cp16(sa + (r * LDW + lc) * 4, ag + (size_t)r * K + lc);
            cp16(sb + (r * LDW + lc) * 4, wg + (size_t)r * K + lc);
        }
        cp_commit();
    }

    float acc[2][8][4];
    #pragma unroll
    for (int mt = 0; mt < 2; mt++)
        #pragma unroll
        for (int nt = 0; nt < 8; nt++)
            #pragma unroll
            for (int q = 0; q < 4; q++) acc[mt][nt][q] = 0.f;

    for (int t = 0; t < ntiles; t++) {
        cp_wait<STAGES - 2>();
        __syncthreads();

        // prefetch tile t+STAGES-1 into the buffer consumed at iter t-1
        const int tp = t + STAGES - 1;
        if (tp < ntiles) {
            const int st = tp % STAGES;
            const float* ag = Ag + (size_t)tp * BKK;
            const float* wg = Wg + (size_t)tp * BKK;
            const uint32_t sa = sA + st * (128 * LDW * 4);
            const uint32_t sb = sB + st * (128 * LDW * 4);
            #pragma unroll
            for (int p = 0; p < 4; p++) {
                const int r = lr + p * 32;
                cp16(sa + (r * LDW + lc) * 4, ag + (size_t)r * K + lc);
                cp16(sb + (r * LDW + lc) * 4, wg + (size_t)r * K + lc);
            }
        }
        cp_commit();

        const uint32_t* a_s = reinterpret_cast<const uint32_t*>(As + (size_t)(t % STAGES) * 128 * LDW);
        const uint32_t* b_s = reinterpret_cast<const uint32_t*>(Bs + (size_t)(t % STAGES) * 128 * LDW);

        #pragma unroll
        for (int ks = 0; ks < 4; ks++) {
            const int k8 = ks * 8;
            uint32_t a[2][4], b[8][2];
            #pragma unroll
            for (int mt = 0; mt < 2; mt++) {
                const int r0 = wm * 32 + mt * 16;
                a[mt][0] = a_s[(r0 +     (lane >> 2)) * LDW + k8 +     (lane & 3)];
                a[mt][1] = a_s[(r0 + 8 + (lane >> 2)) * LDW + k8 +     (lane & 3)];
                a[mt][2] = a_s[(r0 +     (lane >> 2)) * LDW + k8 + 4 + (lane & 3)];
                a[mt][3] = a_s[(r0 + 8 + (lane >> 2)) * LDW + k8 + 4 + (lane & 3)];
            }
            #pragma unroll
            for (int nt = 0; nt < 8; nt++) {
                const int c0 = wn * 64 + nt * 8;
                b[nt][0] = b_s[(c0 + (lane >> 2)) * LDW + k8 +     (lane & 3)];
                b[nt][1] = b_s[(c0 + (lane >> 2)) * LDW + k8 + 4 + (lane & 3)];
            }
            #pragma unroll
            for (int mt = 0; mt < 2; mt++)
                #pragma unroll
                for (int nt = 0; nt < 8; nt++)
                    mma_tf32(acc[mt][nt], a[mt], b[nt]);
        }
        __syncthreads();
    }

    // epilogue straight from registers
    #pragma unroll
    for (int mt = 0; mt < 2; mt++) {
        #pragma unroll
        for (int nt = 0; nt < 8; nt++) {
            const int row = brow + wm * 32 + mt * 16 + (lane >> 2);
            const int col = bcol + wn * 64 + nt * 8 + (lane & 3) * 2;
            const size_t i0 = (size_t)row * N + col;
            const size_t i1 = (size_t)(row + 8) * N + col;
            epi_store<EPI>(out, i0, acc[mt][nt][0], acc[mt][nt][1], aux1, aux2);
            epi_store<EPI>(out, i1, acc[mt][nt][2], acc[mt][nt][3], aux1, aux2);
        }
    }
}

// ---------------- WKV chunked scan ------------------------------------------
__global__ __launch_bounds__(256) void wkv_phase_a(
    const float* __restrict__ k, const float* __restrict__ v,
    const float* __restrict__ td, float* __restrict__ Ca, float* __restrict__ Cb)
{
    const int gid = blockIdx.x * blockDim.x + threadIdx.x;   // < NCH*B*C
    const int c  = gid & (Cq - 1);
    const int r  = gid >> 10;
    const int b  = r & (Bq - 1);
    const int ch = r >> 3;
    const float w  = -expf(td[c]);
    const float dw = expf(w);
    const size_t base = ((size_t)(b * Tq + ch * LCH)) * Cq + c;
    float sa = 0.f, sb = 0.f;
    #pragma unroll 4
    for (int i = 0; i < LCH; i++) {
        const float kt = k[base + (size_t)i * Cq];
        const float vt = v[base + (size_t)i * Cq];
        const float ek = __expf(kt);
        sa = fmaf(dw, sa, ek * vt);
        sb = fmaf(dw, sb, ek);
    }
    Ca[gid] = sa; Cb[gid] = sb;
}

__global__ __launch_bounds__(256) void wkv_scan(
    const float* __restrict__ td,
    const float* __restrict__ Ca, const float* __restrict__ Cb,
    float* __restrict__ Sa, float* __restrict__ Sb)
{
    const int sid = blockIdx.x * blockDim.x + threadIdx.x;   // < B*C
    const int c = sid & (Cq - 1);
    const float w  = -expf(td[c]);
    const float dL = expf((float)LCH * w);
    float sa = 0.f, sb = 0.f;
    #pragma unroll
    for (int ch = 0; ch < NCH; ch++) {
        const int idx = ch * (Bq * Cq) + sid;
        Sa[idx] = sa; Sb[idx] = sb;
        sa = fmaf(dL, sa, Ca[idx]);
        sb = fmaf(dL, sb, Cb[idx]);
    }
}

__global__ __launch_bounds__(256) void wkv_phase_b(
    const float* __restrict__ k, const float* __restrict__ v, const float* __restrict__ sr,
    const float* __restrict__ td, const float* __restrict__ tf,
    const float* __restrict__ Sa, const float* __restrict__ Sb, float* __restrict__ out)
{
    const int gid = blockIdx.x * blockDim.x + threadIdx.x;
    const int c  = gid & (Cq - 1);
    const int r  = gid >> 10;
    const int b  = r & (Bq - 1);
    const int ch = r >> 3;
    const float w  = -expf(td[c]);
    const float dw = expf(w);
    const float eu = expf(tf[c]);
    float a = Sa[gid], bb = Sb[gid];
    const size_t base = ((size_t)(b * Tq + ch * LCH)) * Cq + c;
    #pragma unroll 4
    for (int i = 0; i < LCH; i++) {
        const size_t off = base + (size_t)i * Cq;
        const float kt = k[off];
        const float vt = v[off];
        const float ek = __expf(kt);
        const float euk = eu * ek;
        const float y = (a + euk * vt) / (bb + euk);
        out[off] = rtf(sr[off] * y);          // feeds Wo GEMM only
        a  = fmaf(dw, a,  ek * vt);
        bb = fmaf(dw, bb, ek);
    }
}

// ---------------- launch -----------------------------------------------------
extern "C" void kernel_launch(void* const* d_in, const int* in_sizes, int n_in,
                              void* d_out, int out_size)
{
    const float* x     = (const float*)d_in[0];
    const float* ln1_g = (const float*)d_in[1];
    const float* ln1_b = (const float*)d_in[2];
    const float* ln2_g = (const float*)d_in[3];
    const float* ln2_b = (const float*)d_in[4];
    const float* td    = (const float*)d_in[5];
    const float* tf    = (const float*)d_in[6];
    const float* tmk   = (const float*)d_in[7];
    const float* tmv   = (const float*)d_in[8];
    const float* tmr   = (const float*)d_in[9];
    const float* Wk    = (const float*)d_in[10];
    const float* Wv    = (const float*)d_in[11];
    const float* Wr    = (const float*)d_in[12];
    const float* Wo    = (const float*)d_in[13];
    const float* fmk   = (const float*)d_in[14];
    const float* fmr   = (const float*)d_in[15];
    const float* Fk    = (const float*)d_in[16];
    const float* Fr    = (const float*)d_in[17];
    const float* Fv    = (const float*)d_in[18];
    float* out = (float*)d_out;

    float *xk, *xv, *xr, *k, *v, *sr, *rw, *x1, *fk, *fr, *sg, *kk, *Ca, *Cb, *Sa, *Sb, *wt;
    cudaGetSymbolAddress((void**)&xk, g_xk);
    cudaGetSymbolAddress((void**)&xv, g_xv);
    cudaGetSymbolAddress((void**)&xr, g_xr);
    cudaGetSymbolAddress((void**)&k,  g_k);
    cudaGetSymbolAddress((void**)&v,  g_v);
    cudaGetSymbolAddress((void**)&sr, g_sr);
    cudaGetSymbolAddress((void**)&rw, g_rw);
    cudaGetSymbolAddress((void**)&x1, g_x1);
    cudaGetSymbolAddress((void**)&fk, g_fk);
    cudaGetSymbolAddress((void**)&fr, g_fr);
    cudaGetSymbolAddress((void**)&sg, g_sg);
    cudaGetSymbolAddress((void**)&kk, g_kk);
    cudaGetSymbolAddress((void**)&Ca, g_Ca);
    cudaGetSymbolAddress((void**)&Cb, g_Cb);
    cudaGetSymbolAddress((void**)&Sa, g_Sa);
    cudaGetSymbolAddress((void**)&Sb, g_Sb);
    cudaGetSymbolAddress((void**)&wt, g_wt);

    // rounded weight copies
    const size_t CC = (size_t)Cq * Cq;          // 1M
    const size_t HC = (size_t)HIDq * Cq;        // 4M
    float* rWk = wt;
    float* rWv = wt + CC;
    float* rWr = wt + 2 * CC;
    float* rWo = wt + 3 * CC;
    float* rFr = wt + 4 * CC;
    float* rFk = wt + 5 * CC;
    float* rFv = wt + 5 * CC + HC;

    // opt-in to 108KB dynamic smem (idempotent, host-side, capture-safe)
    cudaFuncSetAttribute(gemm_tf32<0>, cudaFuncAttributeMaxDynamicSharedMemorySize, GEMM_SMEM);
    cudaFuncSetAttribute(gemm_tf32<1>, cudaFuncAttributeMaxDynamicSharedMemorySize, GEMM_SMEM);
    cudaFuncSetAttribute(gemm_tf32<2>, cudaFuncAttributeMaxDynamicSharedMemorySize, GEMM_SMEM);
    cudaFuncSetAttribute(gemm_tf32<3>, cudaFuncAttributeMaxDynamicSharedMemorySize, GEMM_SMEM);
    cudaFuncSetAttribute(gemm_tf32<4>, cudaFuncAttributeMaxDynamicSharedMemorySize, GEMM_SMEM);

    // round weights (RNE->tf32) into scratch
    round_copy4<<<(int)(CC / 4 + 255) / 256, 256>>>(Wk, rWk, (int)(CC / 4));
    round_copy4<<<(int)(CC / 4 + 255) / 256, 256>>>(Wv, rWv, (int)(CC / 4));
    round_copy4<<<(int)(CC / 4 + 255) / 256, 256>>>(Wr, rWr, (int)(CC / 4));
    round_copy4<<<(int)(CC / 4 + 255) / 256, 256>>>(Wo, rWo, (int)(CC / 4));
    round_copy4<<<(int)(CC / 4 + 255) / 256, 256>>>(Fr, rFr, (int)(CC / 4));
    round_copy4<<<(int)(HC / 4 + 255) / 256, 256>>>(Fk, rFk, (int)(HC / 4));
    round_copy4<<<(int)(HC / 4 + 255) / 256, 256>>>(Fv, rFv, (int)(HC / 4));

    const dim3 gC(Cq / BN,  Mq / BM);   // (8, 128)  N=1024
    const dim3 gH(HIDq / BN, Mq / BM);  // (32, 128) N=4096

    // att branch
    ln_mix<3><<<Mq, 256>>>(x, ln1_g, ln1_b, tmk, tmv, tmr, xk, xv, xr);
    gemm_tf32<0><<<gC, 256, GEMM_SMEM>>>(xk, rWk, k,  nullptr, nullptr, Cq, Cq);
    gemm_tf32<0><<<gC, 256, GEMM_SMEM>>>(xv, rWv, v,  nullptr, nullptr, Cq, Cq);
    gemm_tf32<1><<<gC, 256, GEMM_SMEM>>>(xr, rWr, sr, nullptr, nullptr, Cq, Cq);

    wkv_phase_a<<<(NCH * Bq * Cq) / 256, 256>>>(k, v, td, Ca, Cb);
    wkv_scan   <<<(Bq * Cq) / 256, 256>>>(td, Ca, Cb, Sa, Sb);
    wkv_phase_b<<<(NCH * Bq * Cq) / 256, 256>>>(k, v, sr, td, tf, Sa, Sb, rw);

    gemm_tf32<3><<<gC, 256, GEMM_SMEM>>>(rw, rWo, x1, x, nullptr, Cq, Cq);

    // ffn branch
    ln_mix<2><<<Mq, 256>>>(x1, ln2_g, ln2_b, fmk, fmr, nullptr, fk, fr, nullptr);
    gemm_tf32<2><<<gH, 256, GEMM_SMEM>>>(fk, rFk, kk, nullptr, nullptr, HIDq, Cq);
    gemm_tf32<1><<<gC, 256, GEMM_SMEM>>>(fr, rFr, sg, nullptr, nullptr, Cq, Cq);
    gemm_tf32<4><<<gC, 256, GEMM_SMEM>>>(kk, rFv, out, x1, sg, Cq, HIDq);
}